// round 5
// baseline (speedup 1.0000x reference)
#include <cuda_runtime.h>
#include <cuda_bf16.h>
#include <cuda_fp8.h>
#include <math.h>
#include <stdint.h>

// Problem constants (fixed shapes per reference)
#define T_DIM 4096
#define D_DIM 1024
#define BM    128
#define BN    64
#define BK    128                   // fp8 elems per k-tile (128 bytes/row)
#define NT    (D_DIM / BK)          // 8 k-tiles

#define A_OP_BYTES (BM * 128)       // 16384
#define B_OP_BYTES (BN * 128)       // 8192
#define A_BYTES    (4 * A_OP_BYTES) // 65536
#define B_BYTES    (3 * B_OP_BYTES) // 24576
#define STAGE_BYTES (A_BYTES + B_BYTES)  // 90112
#define NSTAGE 2

#define AUX_OFF   (NSTAGE * STAGE_BYTES)    // 180224
#define KEYI_OFF  (AUX_OFF)                 // 128*8
#define KEYJ_OFF  (AUX_OFF + 1024)          // 64*8
#define AMJ_OFF   (AUX_OFF + 1536)          // 64*4
#define AUX_BYTES 1792
#define SMEM_REQ  (AUX_OFF + AUX_BYTES + 1008)

// ---------------- scratch (static device allocations; no cudaMalloc) -------
__device__ unsigned char g_Mb  [T_DIM * D_DIM];   // e4m3 bytes
__device__ unsigned char g_MH  [T_DIM * D_DIM];
__device__ unsigned char g_MH2 [T_DIM * D_DIM];
__device__ unsigned char g_nMH [T_DIM * D_DIM];   // -MH   (exact sign flip)
__device__ unsigned char g_n2MH[T_DIM * D_DIM];   // -2*MH (exact exp shift)
__device__ int                g_am[T_DIM];
__device__ unsigned long long g_rowmin[T_DIM];
__device__ double             g_mse;
__device__ double             g_rowloss;

// ---------------- helpers ---------------------------------------------------
__device__ __forceinline__ unsigned long long pack_key(float s, int idx) {
    unsigned int u = __float_as_uint(s);
    u = (u & 0x80000000u) ? ~u : (u | 0x80000000u);   // order-preserving float->uint
    return ((unsigned long long)u << 32) | (unsigned int)idx;
}
__device__ __forceinline__ unsigned long long ullmin2(unsigned long long a, unsigned long long b) {
    return a < b ? a : b;
}
// fp8 e4m3 MMA: D[16x8] += A[16x32] * B[32x8]
__device__ __forceinline__ void mma16832(float* c, const unsigned* a, const unsigned* b) {
    asm volatile(
        "mma.sync.aligned.m16n8k32.row.col.f32.e4m3.e4m3.f32 "
        "{%0,%1,%2,%3}, {%4,%5,%6,%7}, {%8,%9}, {%0,%1,%2,%3};"
        : "+f"(c[0]), "+f"(c[1]), "+f"(c[2]), "+f"(c[3])
        : "r"(a[0]), "r"(a[1]), "r"(a[2]), "r"(a[3]), "r"(b[0]), "r"(b[1]));
}
__device__ __forceinline__ void ldsm_x4(unsigned* r, unsigned addr) {
    asm volatile("ldmatrix.sync.aligned.m8n8.x4.shared.b16 {%0,%1,%2,%3}, [%4];"
        : "=r"(r[0]), "=r"(r[1]), "=r"(r[2]), "=r"(r[3]) : "r"(addr));
}
__device__ __forceinline__ void cp_async16(unsigned saddr, const void* gaddr) {
    asm volatile("cp.async.cg.shared.global [%0], [%1], 16;" :: "r"(saddr), "l"(gaddr));
}
__device__ __forceinline__ void cp_commit() { asm volatile("cp.async.commit_group;"); }
__device__ __forceinline__ void cp_wait0()  { asm volatile("cp.async.wait_group 0;"); }

__device__ __forceinline__ unsigned char enc_e4m3(float f) {
    __nv_fp8_storage_t s = __nv_cvt_float_to_fp8(f, __NV_SATFINITE, __NV_E4M3);
    return (unsigned char)s;
}
__device__ __forceinline__ float dec_e4m3(unsigned char b) {
    __half_raw hr = __nv_cvt_fp8_to_halfraw((__nv_fp8_storage_t)b, __NV_E4M3);
    return __half2float(*(__half*)&hr);
}

// ---------------- kernel 0: reset accumulators / row-min keys ---------------
__global__ void init_kernel() {
    int t = blockIdx.x * blockDim.x + threadIdx.x;
    if (t < T_DIM) g_rowmin[t] = pack_key(9999.0f, 0);
    if (t == 0) { g_mse = 0.0; g_rowloss = 0.0; }
}

// ---------------- kernel 1: build fp8 operands, am[], masked MSE ------------
__global__ void prep_kernel(const float* __restrict__ X, const float* __restrict__ H,
                            const float* __restrict__ C, const float* __restrict__ M) {
    int i = blockIdx.x;
    int t = threadIdx.x;                       // 256 threads, 4 elems each
    const size_t base = (size_t)i * D_DIM;
    float4 m4 = *(const float4*)(M + base + t * 4);
    float4 h4 = *(const float4*)(H + base + t * 4);
    float4 x4 = *(const float4*)(X + base + t * 4);
    float4 c4 = *(const float4*)(C + base + t * 4);

    float mv[4] = {m4.x, m4.y, m4.z, m4.w};
    float hv[4] = {h4.x, h4.y, h4.z, h4.w};
    float xv[4] = {x4.x, x4.y, x4.z, x4.w};
    float cv[4] = {c4.x, c4.y, c4.z, c4.w};

    unsigned char ob[4], oh[4], oh2[4], onh[4], on2h[4];
    float bestv = 3.4e38f; int besti = 0;
    float msum = 0.f;
    #pragma unroll
    for (int q = 0; q < 4; q++) {
        float mb = (mv[q] > 0.f) ? 1.f : 0.f;
        ob[q]  = enc_e4m3(mb);                        // 0/1 exact
        oh[q]  = enc_e4m3(mb * hv[q]);
        float ohf = dec_e4m3(oh[q]);                  // quantized MH
        oh2[q] = enc_e4m3(mb * hv[q] * hv[q]);
        onh[q]  = oh[q] ^ 0x80;                       // exact -MH (e4m3 sign bit)
        on2h[q] = enc_e4m3(-2.f * ohf);               // exact pow2 scale of quantized MH
        float e = (xv[q] - (hv[q] - cv[q])) * mv[q];
        msum += e * e;
        if (mv[q] < bestv) { bestv = mv[q]; besti = t * 4 + q; }
    }
    *(unsigned*)(g_Mb   + base + t * 4) = *(unsigned*)ob;
    *(unsigned*)(g_MH   + base + t * 4) = *(unsigned*)oh;
    *(unsigned*)(g_MH2  + base + t * 4) = *(unsigned*)oh2;
    *(unsigned*)(g_nMH  + base + t * 4) = *(unsigned*)onh;
    *(unsigned*)(g_n2MH + base + t * 4) = *(unsigned*)on2h;

    __shared__ float sv[256]; __shared__ int si[256]; __shared__ float ss[256];
    sv[t] = bestv; si[t] = besti; ss[t] = msum;
    __syncthreads();
    for (int o = 128; o > 0; o >>= 1) {
        if (t < o) {
            if (sv[t + o] < sv[t] || (sv[t + o] == sv[t] && si[t + o] < si[t])) {
                sv[t] = sv[t + o]; si[t] = si[t + o];
            }
            ss[t] += ss[t + o];
        }
        __syncthreads();
    }
    if (t == 0) {
        g_am[i] = si[0];
        atomicAdd(&g_mse, (double)ss[0]);
    }
}

// ---------------- kernel 2: fused fp8 3-accumulator GEMM + score argmin -----
// acc0 = Mb_i.Mb_j   acc1 = Mb_i.MH_j + (-MH)_i.Mb_j   (= -s1, squared)
// acc2 = MH2_i.Mb_j + (-2MH)_i.MH_j + Mb_i.MH2_j
extern __shared__ char dynsmem[];

__global__ __launch_bounds__(512, 1)
void gemm_kernel() {
    const int bi = blockIdx.y, bj = blockIdx.x;
    if (bj < 2 * bi) return;                    // triangular cover

    const int tid  = threadIdx.x;
    const int lane = tid & 31;
    const int warp = tid >> 5;
    const int wm = warp >> 1;                   // 0..7 -> 16-row slab
    const int wn = warp & 1;                    // 0..1 -> 32-col slab
    const int g  = lane >> 2;
    const int tg = lane & 3;
    const int ib = bi * BM, jb = bj * BN;

    unsigned raw = (unsigned)__cvta_generic_to_shared(dynsmem);
    unsigned sb0 = (raw + 1023u) & ~1023u;      // 1024-aligned stage area
    char* auxg = dynsmem + (sb0 - raw);
    unsigned long long* keyI = (unsigned long long*)(auxg + KEYI_OFF);
    unsigned long long* keyJ = (unsigned long long*)(auxg + KEYJ_OFF);
    int* s_amJ = (int*)(auxg + AMJ_OFF);

    if (tid < BM)                 keyI[tid]      = ~0ull;
    else if (tid < BM + BN) {     keyJ[tid - BM] = ~0ull; s_amJ[tid - BM] = g_am[jb + tid - BM]; }

    float acc[3][4][4];
    #pragma unroll
    for (int p = 0; p < 3; p++)
        #pragma unroll
        for (int b = 0; b < 4; b++)
            #pragma unroll
            for (int c = 0; c < 4; c++) acc[p][b][c] = 0.f;

    const unsigned char* const matsA[4] = {g_Mb, g_nMH, g_n2MH, g_MH2};
    const unsigned char* const matsB[3] = {g_Mb, g_MH, g_MH2};

    // ---- stage loader: swizzled 16B chunks (128B = BK fp8 per row) ----------
    auto load_stage = [&](int stage, int kt) {
        unsigned sb = sb0 + stage * STAGE_BYTES;
        int kcol = kt * BK;
        #pragma unroll
        for (int it = 0; it < 8; it++) {           // A: 4 ops x 128 rows x 8 chunks
            int id = tid + it * 512;
            int op = id >> 10, rem = id & 1023, r = rem >> 3, c = rem & 7;
            const unsigned char* gp = matsA[op] + (size_t)(ib + r) * D_DIM + kcol + c * 16;
            cp_async16(sb + op * A_OP_BYTES + r * 128 + (((unsigned)(c ^ (r & 7))) << 4), gp);
        }
        #pragma unroll
        for (int it = 0; it < 3; it++) {           // B: 3 ops x 64 rows x 8 chunks
            int id = tid + it * 512;
            int op = id >> 9, rem = id & 511, r = rem >> 3, c = rem & 7;
            const unsigned char* gp = matsB[op] + (size_t)(jb + r) * D_DIM + kcol + c * 16;
            cp_async16(sb + A_BYTES + op * B_OP_BYTES + r * 128 + (((unsigned)(c ^ (r & 7))) << 4), gp);
        }
    };

    // ldmatrix per-lane geometry (byte-identical to bf16 case)
    const int a_row  = wm * 16 + (lane & 15);
    const int a_half = lane >> 4;
    const int b_lrow = (lane & 7) + ((lane >> 4) << 3);
    const int b_half = (lane >> 3) & 1;

    load_stage(0, 0);
    cp_commit();

    #pragma unroll 1
    for (int kt = 0; kt < NT; kt++) {
        cp_wait0();                               // stage kt resident
        __syncthreads();                          // everyone done with stage kt-1 buffer
        if (kt + 1 < NT) { load_stage((kt + 1) & 1, kt + 1); cp_commit(); }

        unsigned sb = sb0 + (kt & 1) * STAGE_BYTES;
        #pragma unroll
        for (int kk8 = 0; kk8 < 8; kk8 += 2) {    // 4 k-chunks of 32 fp8
            unsigned bf[3][4][2];
            #pragma unroll
            for (int m = 0; m < 3; m++)
                #pragma unroll
                for (int ng = 0; ng < 2; ng++) {
                    int row = wn * 32 + ng * 16 + b_lrow;
                    unsigned addr = sb + A_BYTES + m * B_OP_BYTES + row * 128
                                  + (((unsigned)((kk8 + b_half) ^ (row & 7))) << 4);
                    unsigned r[4]; ldsm_x4(r, addr);
                    bf[m][2 * ng][0] = r[0]; bf[m][2 * ng][1] = r[1];
                    bf[m][2 * ng + 1][0] = r[2]; bf[m][2 * ng + 1][1] = r[3];
                }
            unsigned arow_off = a_row * 128 + (((unsigned)((kk8 + a_half) ^ (a_row & 7))) << 4);
            {   // A0 = Mb: acc0 += A0*B0, acc1 += A0*B1, acc2 += A0*B2
                unsigned a[4]; ldsm_x4(a, sb + 0 * A_OP_BYTES + arow_off);
                #pragma unroll
                for (int nf = 0; nf < 4; nf++) {
                    mma16832(acc[0][nf], a, bf[0][nf]);
                    mma16832(acc[1][nf], a, bf[1][nf]);
                    mma16832(acc[2][nf], a, bf[2][nf]);
                }
            }
            {   // A1 = -MH: acc1 += A1*B0
                unsigned a[4]; ldsm_x4(a, sb + 1 * A_OP_BYTES + arow_off);
                #pragma unroll
                for (int nf = 0; nf < 4; nf++) mma16832(acc[1][nf], a, bf[0][nf]);
            }
            {   // A2 = -2MH: acc2 += A2*B1
                unsigned a[4]; ldsm_x4(a, sb + 2 * A_OP_BYTES + arow_off);
                #pragma unroll
                for (int nf = 0; nf < 4; nf++) mma16832(acc[2][nf], a, bf[1][nf]);
            }
            {   // A3 = MH2: acc2 += A3*B0
                unsigned a[4]; ldsm_x4(a, sb + 3 * A_OP_BYTES + arow_off);
                #pragma unroll
                for (int nf = 0; nf < 4; nf++) mma16832(acc[2][nf], a, bf[0][nf]);
            }
        }
    }

    // ---- epilogue: score + packed (score,index) min-reduction --------------
    const int i0 = ib + wm * 16 + g;
    const int am0 = g_am[i0];
    const int am1 = g_am[i0 + 8];
    unsigned long long rk[2] = {~0ull, ~0ull};
    unsigned long long ck[4][2] = {{~0ull,~0ull},{~0ull,~0ull},{~0ull,~0ull},{~0ull,~0ull}};

    #pragma unroll
    for (int nf = 0; nf < 4; nf++)
        #pragma unroll
        for (int idx = 0; idx < 4; idx++) {
            int rr = idx >> 1, c = idx & 1;
            int i = i0 + rr * 8;
            int jl = wn * 32 + nf * 8 + tg * 2 + c;
            int j = jb + jl;
            float nn = acc[0][nf][idx];
            int ami = rr ? am1 : am0;
            if (i != j && nn > 1.5f && ami != s_amJ[jl]) {
                float ns = fmaxf(nn, 2.f);
                float s1 = acc[1][nf][idx];
                float s2 = acc[2][nf][idx];
                float var = (s2 - s1 * s1 / ns) / (ns - 1.f);
                rk[rr] = ullmin2(rk[rr], pack_key(var, j));
                ck[nf][c] = ullmin2(ck[nf][c], pack_key(var, i));
            }
        }

    #pragma unroll
    for (int rr = 0; rr < 2; rr++) {
        unsigned long long v = rk[rr];
        v = ullmin2(v, __shfl_xor_sync(0xffffffffu, v, 1));
        v = ullmin2(v, __shfl_xor_sync(0xffffffffu, v, 2));
        if (tg == 0 && v != ~0ull)
            atomicMin(&keyI[wm * 16 + rr * 8 + g], v);
    }
    #pragma unroll
    for (int nf = 0; nf < 4; nf++)
        #pragma unroll
        for (int c = 0; c < 2; c++) {
            unsigned long long v = ck[nf][c];
            v = ullmin2(v, __shfl_down_sync(0xffffffffu, v, 4));
            v = ullmin2(v, __shfl_down_sync(0xffffffffu, v, 8));
            v = ullmin2(v, __shfl_down_sync(0xffffffffu, v, 16));
            if (g == 0 && v != ~0ull)
                atomicMin(&keyJ[wn * 32 + nf * 8 + tg * 2 + c], v);
        }

    __syncthreads();
    if (tid < BM) {
        if (keyI[tid] != ~0ull) atomicMin(&g_rowmin[ib + tid], keyI[tid]);
    } else if (tid < BM + BN) {
        if (keyJ[tid - BM] != ~0ull) atomicMin(&g_rowmin[jb + tid - BM], keyJ[tid - BM]);
    }
}

// ---------------- kernel 3: row loss ||H[i] - H[argmin]|| -------------------
__global__ void rowloss_kernel(const float* __restrict__ H) {
    int i = blockIdx.x;
    int t = threadIdx.x;                           // 256 threads x float4
    int j = (int)(g_rowmin[i] & 0xFFFFFFFFull);
    float4 va = *(const float4*)(H + (size_t)i * D_DIM + t * 4);
    float4 vb = *(const float4*)(H + (size_t)j * D_DIM + t * 4);
    float dx = va.x - vb.x, dy = va.y - vb.y, dz = va.z - vb.z, dw = va.w - vb.w;
    float s = dx * dx + dy * dy + dz * dz + dw * dw;
    __shared__ float sh[256];
    sh[t] = s; __syncthreads();
    for (int o = 128; o > 0; o >>= 1) { if (t < o) sh[t] += sh[t + o]; __syncthreads(); }
    if (t == 0) atomicAdd(&g_rowloss, sqrt((double)sh[0]));
}

// ---------------- kernel 4: combine -----------------------------------------
__global__ void final_kernel(float* out) {
    out[0] = (float)(g_mse + 10.0 * g_rowloss);
}

// ---------------- launch ------------------------------------------------------
extern "C" void kernel_launch(void* const* d_in, const int* in_sizes, int n_in,
                              void* d_out, int out_size) {
    const float* X = (const float*)d_in[0];
    const float* H = (const float*)d_in[1];
    const float* C = (const float*)d_in[2];
    const float* M = (const float*)d_in[3];
    (void)in_sizes; (void)n_in; (void)out_size;

    cudaFuncSetAttribute(gemm_kernel, cudaFuncAttributeMaxDynamicSharedMemorySize, SMEM_REQ);

    init_kernel<<<(T_DIM + 255) / 256, 256>>>();
    prep_kernel<<<T_DIM, 256>>>(X, H, C, M);
    dim3 grid(T_DIM / BN, T_DIM / BM);             // (64, 32), bj < 2*bi exits early
    gemm_kernel<<<grid, 512, SMEM_REQ>>>();
    rowloss_kernel<<<T_DIM, 256>>>(H);
    final_kernel<<<1, 1>>>((float*)d_out);
}

// round 6
// speedup vs baseline: 1.2335x; 1.2335x over previous
#include <cuda_runtime.h>
#include <cuda_bf16.h>
#include <math.h>
#include <stdint.h>

// Problem constants (fixed shapes per reference)
#define T_DIM 4096
#define D_DIM 1024
#define BM    64
#define BN    64
#define BK    64
#define NT    (D_DIM / BK)          // 16 k-tiles

#define OP_BYTES   (64 * 128)       // one operand tile: 64 rows x 128B (BK=64 bf16)
#define A_BYTES    (3 * OP_BYTES)   // 24576 (Mb, MH, MH2 rows ib)
#define B_OFF      A_BYTES
#define STAGE_BYTES (6 * OP_BYTES)  // 49152
#define NSTAGE 2

#define AUX_OFF   (NSTAGE * STAGE_BYTES)    // 98304
#define KEYI_OFF  (AUX_OFF)                 // 64*8 = 512
#define KEYJ_OFF  (AUX_OFF + 512)           // 64*8 = 512
#define AMJ_OFF   (AUX_OFF + 1024)          // 64*4 = 256
#define AUX_BYTES 1280
#define SMEM_REQ  (AUX_OFF + AUX_BYTES + 1008)

// ---------------- scratch (static device allocations; no cudaMalloc) -------
__device__ __nv_bfloat16 g_Mb [T_DIM * D_DIM];
__device__ __nv_bfloat16 g_MH [T_DIM * D_DIM];
__device__ __nv_bfloat16 g_MH2[T_DIM * D_DIM];
__device__ int                g_am[T_DIM];
__device__ unsigned long long g_rowmin[T_DIM];
__device__ double             g_mse;
__device__ double             g_rowloss;

// ---------------- helpers ---------------------------------------------------
__device__ __forceinline__ unsigned long long pack_key(float s, int idx) {
    unsigned int u = __float_as_uint(s);
    u = (u & 0x80000000u) ? ~u : (u | 0x80000000u);   // order-preserving float->uint
    return ((unsigned long long)u << 32) | (unsigned int)idx;
}
__device__ __forceinline__ unsigned long long ullmin2(unsigned long long a, unsigned long long b) {
    return a < b ? a : b;
}
__device__ __forceinline__ void mma16816(float* c, const unsigned* a, const unsigned* b) {
    asm volatile(
        "mma.sync.aligned.m16n8k16.row.col.f32.bf16.bf16.f32 "
        "{%0,%1,%2,%3}, {%4,%5,%6,%7}, {%8,%9}, {%0,%1,%2,%3};"
        : "+f"(c[0]), "+f"(c[1]), "+f"(c[2]), "+f"(c[3])
        : "r"(a[0]), "r"(a[1]), "r"(a[2]), "r"(a[3]), "r"(b[0]), "r"(b[1]));
}
__device__ __forceinline__ void ldsm_x4(unsigned* r, unsigned addr) {
    asm volatile("ldmatrix.sync.aligned.m8n8.x4.shared.b16 {%0,%1,%2,%3}, [%4];"
        : "=r"(r[0]), "=r"(r[1]), "=r"(r[2]), "=r"(r[3]) : "r"(addr));
}
__device__ __forceinline__ void cp_async16(unsigned saddr, const void* gaddr) {
    asm volatile("cp.async.cg.shared.global [%0], [%1], 16;" :: "r"(saddr), "l"(gaddr));
}
__device__ __forceinline__ void cp_commit() { asm volatile("cp.async.commit_group;"); }
__device__ __forceinline__ void cp_wait1()  { asm volatile("cp.async.wait_group 1;"); }
__device__ __forceinline__ void cp_wait0()  { asm volatile("cp.async.wait_group 0;"); }

// ---------------- kernel 0: reset accumulators / row-min keys ---------------
__global__ void init_kernel() {
    int t = blockIdx.x * blockDim.x + threadIdx.x;
    if (t < T_DIM) g_rowmin[t] = pack_key(9999.0f, 0);
    if (t == 0) { g_mse = 0.0; g_rowloss = 0.0; }
}

// ---------------- kernel 1: build bf16 operands, am[], masked MSE -----------
__global__ void prep_kernel(const float* __restrict__ X, const float* __restrict__ H,
                            const float* __restrict__ C, const float* __restrict__ M) {
    int i = blockIdx.x;
    int t = threadIdx.x;                       // 256 threads, 4 elems each
    const size_t base = (size_t)i * D_DIM;
    float4 m4 = *(const float4*)(M + base + t * 4);
    float4 h4 = *(const float4*)(H + base + t * 4);
    float4 x4 = *(const float4*)(X + base + t * 4);
    float4 c4 = *(const float4*)(C + base + t * 4);

    float mv[4] = {m4.x, m4.y, m4.z, m4.w};
    float hv[4] = {h4.x, h4.y, h4.z, h4.w};
    float xv[4] = {x4.x, x4.y, x4.z, x4.w};
    float cv[4] = {c4.x, c4.y, c4.z, c4.w};

    __nv_bfloat16 ob[4], oh[4], oh2[4];
    float bestv = 3.4e38f; int besti = 0;
    float msum = 0.f;
    #pragma unroll
    for (int q = 0; q < 4; q++) {
        float mb = (mv[q] > 0.f) ? 1.f : 0.f;
        ob[q]  = __float2bfloat16(mb);
        oh[q]  = __float2bfloat16(mb * hv[q]);
        oh2[q] = __float2bfloat16(mb * hv[q] * hv[q]);
        float e = (xv[q] - (hv[q] - cv[q])) * mv[q];
        msum += e * e;
        if (mv[q] < bestv) { bestv = mv[q]; besti = t * 4 + q; }
    }
    *(uint2*)(g_Mb  + base + t * 4) = *(uint2*)ob;
    *(uint2*)(g_MH  + base + t * 4) = *(uint2*)oh;
    *(uint2*)(g_MH2 + base + t * 4) = *(uint2*)oh2;

    __shared__ float sv[256]; __shared__ int si[256]; __shared__ float ss[256];
    sv[t] = bestv; si[t] = besti; ss[t] = msum;
    __syncthreads();
    for (int o = 128; o > 0; o >>= 1) {
        if (t < o) {
            if (sv[t + o] < sv[t] || (sv[t + o] == sv[t] && si[t + o] < si[t])) {
                sv[t] = sv[t + o]; si[t] = si[t + o];
            }
            ss[t] += ss[t + o];
        }
        __syncthreads();
    }
    if (t == 0) {
        g_am[i] = si[0];
        atomicAdd(&g_mse, (double)ss[0]);
    }
}

// ---------------- kernel 2: fused 3-accumulator GEMM + score argmin ---------
// acc0 = Mb_i.Mb_j
// acc1 = Mb_i.MH_j + (-MH)_i.Mb_j         (= -s1, used squared; -MH derived by XOR)
// acc2 = MH2_i.Mb_j + (-2MH)_i.MH_j + Mb_i.MH2_j   (-2MH = hmul2(-MH, 2), exact)
extern __shared__ char dynsmem[];

__global__ __launch_bounds__(128, 2)
void gemm_kernel() {
    const int bi = blockIdx.y, bj = blockIdx.x;
    if (bj < bi) return;                        // upper triangle incl diagonal

    const int tid  = threadIdx.x;
    const int lane = tid & 31;
    const int warp = tid >> 5;                  // 0..3
    const int wm = warp >> 1;                   // 0..1 -> 32-row slab
    const int wn = warp & 1;                    // 0..1 -> 32-col slab
    const int g  = lane >> 2;
    const int tg = lane & 3;
    const int ib = bi * BM, jb = bj * BN;

    unsigned raw = (unsigned)__cvta_generic_to_shared(dynsmem);
    unsigned sb0 = (raw + 1023u) & ~1023u;      // 1024-aligned stage area
    char* auxg = dynsmem + (sb0 - raw);
    unsigned long long* keyI = (unsigned long long*)(auxg + KEYI_OFF);
    unsigned long long* keyJ = (unsigned long long*)(auxg + KEYJ_OFF);
    int* s_amJ = (int*)(auxg + AMJ_OFF);

    if (tid < BM)            keyI[tid] = ~0ull;
    else {                   keyJ[tid - BM] = ~0ull; s_amJ[tid - BM] = g_am[jb + tid - BM]; }

    float acc[3][2][4][4];
    #pragma unroll
    for (int p = 0; p < 3; p++)
        #pragma unroll
        for (int a = 0; a < 2; a++)
            #pragma unroll
            for (int b = 0; b < 4; b++)
                #pragma unroll
                for (int c = 0; c < 4; c++) acc[p][a][b][c] = 0.f;

    const __nv_bfloat16* const mats[3] = {g_Mb, g_MH, g_MH2};

    // ---- stage loader: 6 tiles (3 A rows=ib, 3 B rows=jb) x 64 rows x 8 chunks
    auto load_stage = [&](int stage, int kt) {
        unsigned sb = sb0 + stage * STAGE_BYTES;
        int kcol = kt * BK;
        #pragma unroll
        for (int it = 0; it < 24; it++) {          // 6*64*8 = 3072 chunks / 128 thr
            int id = tid + it * 128;
            int op = id >> 9;                      // 0..5
            int rem = id & 511, r = rem >> 3, c = rem & 7;
            int rowbase = (op < 3) ? ib : jb;
            const __nv_bfloat16* gp = mats[op % 3] + (size_t)(rowbase + r) * D_DIM + kcol + c * 8;
            cp_async16(sb + op * OP_BYTES + r * 128 + (((unsigned)(c ^ (r & 7))) << 4), gp);
        }
    };

    // ldmatrix per-lane geometry
    const int a_lrow = lane & 15;
    const int a_half = lane >> 4;
    const int b_lrow = (lane & 7) + ((lane >> 4) << 3);
    const int b_half = (lane >> 3) & 1;
    const unsigned two2 = 0x40004000u;              // bf16x2 {2,2}

    load_stage(0, 0);
    cp_commit();

    #pragma unroll 1
    for (int kt = 0; kt < NT; kt++) {
        if (kt + 1 < NT) { load_stage((kt + 1) & 1, kt + 1); cp_commit(); cp_wait1(); }
        else             { cp_wait0(); }
        __syncthreads();

        unsigned sb = sb0 + (kt & 1) * STAGE_BYTES;
        #pragma unroll
        for (int kk8 = 0; kk8 < 8; kk8 += 2) {      // 4 k-chunks of 16
            // B fragments: 3 ops x 4 nf x 2 regs
            unsigned bf[3][4][2];
            #pragma unroll
            for (int m = 0; m < 3; m++)
                #pragma unroll
                for (int ng = 0; ng < 2; ng++) {
                    int row = wn * 32 + ng * 16 + b_lrow;
                    unsigned addr = sb + B_OFF + m * OP_BYTES + row * 128
                                  + (((unsigned)((kk8 + b_half) ^ (row & 7))) << 4);
                    unsigned r[4]; ldsm_x4(r, addr);
                    bf[m][2 * ng][0] = r[0]; bf[m][2 * ng][1] = r[1];
                    bf[m][2 * ng + 1][0] = r[2]; bf[m][2 * ng + 1][1] = r[3];
                }
            // A fragments per mf row-slab
            #pragma unroll
            for (int mf = 0; mf < 2; mf++) {
                int row = wm * 32 + mf * 16 + a_lrow;
                unsigned arow_off = row * 128 + (((unsigned)((kk8 + a_half) ^ (row & 7))) << 4);
                {   // A = Mb: acc0 += A*B0, acc1 += A*B1, acc2 += A*B2
                    unsigned a[4]; ldsm_x4(a, sb + 0 * OP_BYTES + arow_off);
                    #pragma unroll
                    for (int nf = 0; nf < 4; nf++) {
                        mma16816(acc[0][mf][nf], a, bf[0][nf]);
                        mma16816(acc[1][mf][nf], a, bf[1][nf]);
                        mma16816(acc[2][mf][nf], a, bf[2][nf]);
                    }
                }
                {   // A = MH -> -MH (XOR, exact): acc1 += (-MH)*B0
                    // then *2 (hmul2, exact): acc2 += (-2MH)*B1
                    unsigned a[4]; ldsm_x4(a, sb + 1 * OP_BYTES + arow_off);
                    #pragma unroll
                    for (int q = 0; q < 4; q++) a[q] ^= 0x80008000u;
                    #pragma unroll
                    for (int nf = 0; nf < 4; nf++) mma16816(acc[1][mf][nf], a, bf[0][nf]);
                    #pragma unroll
                    for (int q = 0; q < 4; q++) {
                        __nv_bfloat162 v = *reinterpret_cast<__nv_bfloat162*>(&a[q]);
                        v = __hmul2(v, *reinterpret_cast<const __nv_bfloat162*>(&two2));
                        a[q] = *reinterpret_cast<unsigned*>(&v);
                    }
                    #pragma unroll
                    for (int nf = 0; nf < 4; nf++) mma16816(acc[2][mf][nf], a, bf[1][nf]);
                }
                {   // A = MH2: acc2 += A*B0
                    unsigned a[4]; ldsm_x4(a, sb + 2 * OP_BYTES + arow_off);
                    #pragma unroll
                    for (int nf = 0; nf < 4; nf++) mma16816(acc[2][mf][nf], a, bf[0][nf]);
                }
            }
        }
        __syncthreads();                            // protect stage before overwrite
    }

    // ---- epilogue: score + packed (score,index) min-reduction --------------
    unsigned long long rk[2][2] = {{~0ull, ~0ull}, {~0ull, ~0ull}};   // [mf][rr]
    unsigned long long ck[4][2] = {{~0ull,~0ull},{~0ull,~0ull},{~0ull,~0ull},{~0ull,~0ull}};

    #pragma unroll
    for (int mf = 0; mf < 2; mf++) {
        const int i0 = ib + wm * 32 + mf * 16 + g;
        const int am0 = g_am[i0];
        const int am1 = g_am[i0 + 8];
        #pragma unroll
        for (int nf = 0; nf < 4; nf++)
            #pragma unroll
            for (int idx = 0; idx < 4; idx++) {
                int rr = idx >> 1, c = idx & 1;
                int i = i0 + rr * 8;
                int jl = wn * 32 + nf * 8 + tg * 2 + c;
                int j = jb + jl;
                float nn = acc[0][mf][nf][idx];
                int ami = rr ? am1 : am0;
                if (i != j && nn > 1.5f && ami != s_amJ[jl]) {
                    float ns = fmaxf(nn, 2.f);
                    float s1 = acc[1][mf][nf][idx];
                    float s2 = acc[2][mf][nf][idx];
                    float var = (s2 - s1 * s1 / ns) / (ns - 1.f);
                    rk[mf][rr] = ullmin2(rk[mf][rr], pack_key(var, j));
                    ck[nf][c]  = ullmin2(ck[nf][c],  pack_key(var, i));
                }
            }
    }

    // row-side: min over quad lanes (same row, different cols)
    #pragma unroll
    for (int mf = 0; mf < 2; mf++)
        #pragma unroll
        for (int rr = 0; rr < 2; rr++) {
            unsigned long long v = rk[mf][rr];
            v = ullmin2(v, __shfl_xor_sync(0xffffffffu, v, 1));
            v = ullmin2(v, __shfl_xor_sync(0xffffffffu, v, 2));
            if (tg == 0 && v != ~0ull)
                atomicMin(&keyI[wm * 32 + mf * 16 + rr * 8 + g], v);
        }
    // col-side: min over lanes sharing tg (same cols, different rows)
    #pragma unroll
    for (int nf = 0; nf < 4; nf++)
        #pragma unroll
        for (int c = 0; c < 2; c++) {
            unsigned long long v = ck[nf][c];
            v = ullmin2(v, __shfl_down_sync(0xffffffffu, v, 4));
            v = ullmin2(v, __shfl_down_sync(0xffffffffu, v, 8));
            v = ullmin2(v, __shfl_down_sync(0xffffffffu, v, 16));
            if (g == 0 && v != ~0ull)
                atomicMin(&keyJ[wn * 32 + nf * 8 + tg * 2 + c], v);
        }

    __syncthreads();
    if (tid < BM) {
        if (keyI[tid] != ~0ull) atomicMin(&g_rowmin[ib + tid], keyI[tid]);
    } else {
        if (keyJ[tid - BM] != ~0ull) atomicMin(&g_rowmin[jb + tid - BM], keyJ[tid - BM]);
    }
}

// ---------------- kernel 3: row loss ||H[i] - H[argmin]|| -------------------
__global__ void rowloss_kernel(const float* __restrict__ H) {
    int i = blockIdx.x;
    int t = threadIdx.x;                           // 256 threads x float4
    int j = (int)(g_rowmin[i] & 0xFFFFFFFFull);
    float4 va = *(const float4*)(H + (size_t)i * D_DIM + t * 4);
    float4 vb = *(const float4*)(H + (size_t)j * D_DIM + t * 4);
    float dx = va.x - vb.x, dy = va.y - vb.y, dz = va.z - vb.z, dw = va.w - vb.w;
    float s = dx * dx + dy * dy + dz * dz + dw * dw;
    __shared__ float sh[256];
    sh[t] = s; __syncthreads();
    for (int o = 128; o > 0; o >>= 1) { if (t < o) sh[t] += sh[t + o]; __syncthreads(); }
    if (t == 0) atomicAdd(&g_rowloss, sqrt((double)sh[0]));
}

// ---------------- kernel 4: combine -----------------------------------------
__global__ void final_kernel(float* out) {
    out[0] = (float)(g_mse + 10.0 * g_rowloss);
}

// ---------------- launch ------------------------------------------------------
extern "C" void kernel_launch(void* const* d_in, const int* in_sizes, int n_in,
                              void* d_out, int out_size) {
    const float* X = (const float*)d_in[0];
    const float* H = (const float*)d_in[1];
    const float* C = (const float*)d_in[2];
    const float* M = (const float*)d_in[3];
    (void)in_sizes; (void)n_in; (void)out_size;

    cudaFuncSetAttribute(gemm_kernel, cudaFuncAttributeMaxDynamicSharedMemorySize, SMEM_REQ);

    init_kernel<<<(T_DIM + 255) / 256, 256>>>();
    prep_kernel<<<T_DIM, 256>>>(X, H, C, M);
    dim3 grid(T_DIM / BN, T_DIM / BM);             // (64, 64), bj < bi exits early
    gemm_kernel<<<grid, 128, SMEM_REQ>>>();
    rowloss_kernel<<<T_DIM, 256>>>(H);
    final_kernel<<<1, 1>>>((float*)d_out);
}

// round 7
// speedup vs baseline: 1.3217x; 1.0715x over previous
#include <cuda_runtime.h>
#include <cuda_bf16.h>
#include <math.h>
#include <stdint.h>

// Problem constants (fixed shapes per reference)
#define T_DIM 4096
#define D_DIM 1024
#define BM    64
#define BN    64
#define BK    64
#define NT    (D_DIM / BK)          // 16 k-tiles

#define OP_BYTES   (64 * 128)       // one operand tile: 64 rows x 128B (BK=64 bf16)
#define A_BYTES    (3 * OP_BYTES)   // 24576 (Mb, MH, MH2 rows ib)
#define B_OFF      A_BYTES
#define STAGE_BYTES (6 * OP_BYTES)  // 49152
#define NSTAGE 2

#define AUX_OFF   (NSTAGE * STAGE_BYTES)    // 98304
#define KEYI_OFF  (AUX_OFF)                 // 64*8 = 512
#define KEYJ_OFF  (AUX_OFF + 512)           // 64*8 = 512
#define AMJ_OFF   (AUX_OFF + 1024)          // 64*4 = 256
#define AUX_BYTES 1280
#define SMEM_REQ  (AUX_OFF + AUX_BYTES + 1008)

// ---------------- scratch (static device allocations; no cudaMalloc) -------
__device__ __nv_bfloat16 g_Mb [T_DIM * D_DIM];
__device__ __nv_bfloat16 g_MH [T_DIM * D_DIM];
__device__ __nv_bfloat16 g_MH2[T_DIM * D_DIM];
__device__ int                g_am[T_DIM];
__device__ unsigned long long g_rowmin[T_DIM];
__device__ double             g_mse;
__device__ double             g_rowloss;

// ---------------- helpers ---------------------------------------------------
__device__ __forceinline__ unsigned long long pack_key(float s, int idx) {
    unsigned int u = __float_as_uint(s);
    u = (u & 0x80000000u) ? ~u : (u | 0x80000000u);   // order-preserving float->uint
    return ((unsigned long long)u << 32) | (unsigned int)idx;
}
__device__ __forceinline__ unsigned long long ullmin2(unsigned long long a, unsigned long long b) {
    return a < b ? a : b;
}
__device__ __forceinline__ void mma16816(float* c, const unsigned* a, const unsigned* b) {
    asm volatile(
        "mma.sync.aligned.m16n8k16.row.col.f32.bf16.bf16.f32 "
        "{%0,%1,%2,%3}, {%4,%5,%6,%7}, {%8,%9}, {%0,%1,%2,%3};"
        : "+f"(c[0]), "+f"(c[1]), "+f"(c[2]), "+f"(c[3])
        : "r"(a[0]), "r"(a[1]), "r"(a[2]), "r"(a[3]), "r"(b[0]), "r"(b[1]));
}
__device__ __forceinline__ void ldsm_x4(unsigned* r, unsigned addr) {
    asm volatile("ldmatrix.sync.aligned.m8n8.x4.shared.b16 {%0,%1,%2,%3}, [%4];"
        : "=r"(r[0]), "=r"(r[1]), "=r"(r[2]), "=r"(r[3]) : "r"(addr));
}
__device__ __forceinline__ void cp_async16(unsigned saddr, const void* gaddr) {
    asm volatile("cp.async.cg.shared.global [%0], [%1], 16;" :: "r"(saddr), "l"(gaddr));
}
__device__ __forceinline__ void cp_commit() { asm volatile("cp.async.commit_group;"); }
__device__ __forceinline__ void cp_wait1()  { asm volatile("cp.async.wait_group 1;"); }
__device__ __forceinline__ void cp_wait0()  { asm volatile("cp.async.wait_group 0;"); }

__device__ __forceinline__ unsigned hadd2u(unsigned a, unsigned b) {
    __nv_bfloat162 va = *reinterpret_cast<__nv_bfloat162*>(&a);
    __nv_bfloat162 vb = *reinterpret_cast<__nv_bfloat162*>(&b);
    __nv_bfloat162 r = __hadd2(va, vb);
    return *reinterpret_cast<unsigned*>(&r);
}
__device__ __forceinline__ unsigned hsub2u(unsigned a, unsigned b) {
    __nv_bfloat162 va = *reinterpret_cast<__nv_bfloat162*>(&a);
    __nv_bfloat162 vb = *reinterpret_cast<__nv_bfloat162*>(&b);
    __nv_bfloat162 r = __hsub2(va, vb);
    return *reinterpret_cast<unsigned*>(&r);
}

// ---------------- kernel 0: reset accumulators / row-min keys ---------------
__global__ void init_kernel() {
    int t = blockIdx.x * blockDim.x + threadIdx.x;
    if (t < T_DIM) g_rowmin[t] = pack_key(9999.0f, 0);
    if (t == 0) { g_mse = 0.0; g_rowloss = 0.0; }
}

// ---------------- kernel 1: build bf16 operands, am[], masked MSE -----------
__global__ void prep_kernel(const float* __restrict__ X, const float* __restrict__ H,
                            const float* __restrict__ C, const float* __restrict__ M) {
    int i = blockIdx.x;
    int t = threadIdx.x;                       // 256 threads, 4 elems each
    const size_t base = (size_t)i * D_DIM;
    float4 m4 = *(const float4*)(M + base + t * 4);
    float4 h4 = *(const float4*)(H + base + t * 4);
    float4 x4 = *(const float4*)(X + base + t * 4);
    float4 c4 = *(const float4*)(C + base + t * 4);

    float mv[4] = {m4.x, m4.y, m4.z, m4.w};
    float hv[4] = {h4.x, h4.y, h4.z, h4.w};
    float xv[4] = {x4.x, x4.y, x4.z, x4.w};
    float cv[4] = {c4.x, c4.y, c4.z, c4.w};

    __nv_bfloat16 ob[4], oh[4], oh2[4];
    float bestv = 3.4e38f; int besti = 0;
    float msum = 0.f;
    #pragma unroll
    for (int q = 0; q < 4; q++) {
        float mb = (mv[q] > 0.f) ? 1.f : 0.f;
        ob[q]  = __float2bfloat16(mb);
        oh[q]  = __float2bfloat16(mb * hv[q]);
        oh2[q] = __float2bfloat16(mb * hv[q] * hv[q]);
        float e = (xv[q] - (hv[q] - cv[q])) * mv[q];
        msum += e * e;
        if (mv[q] < bestv) { bestv = mv[q]; besti = t * 4 + q; }
    }
    *(uint2*)(g_Mb  + base + t * 4) = *(uint2*)ob;
    *(uint2*)(g_MH  + base + t * 4) = *(uint2*)oh;
    *(uint2*)(g_MH2 + base + t * 4) = *(uint2*)oh2;

    __shared__ float sv[256]; __shared__ int si[256]; __shared__ float ss[256];
    sv[t] = bestv; si[t] = besti; ss[t] = msum;
    __syncthreads();
    for (int o = 128; o > 0; o >>= 1) {
        if (t < o) {
            if (sv[t + o] < sv[t] || (sv[t + o] == sv[t] && si[t + o] < si[t])) {
                sv[t] = sv[t + o]; si[t] = si[t + o];
            }
            ss[t] += ss[t + o];
        }
        __syncthreads();
    }
    if (t == 0) {
        g_am[i] = si[0];
        atomicAdd(&g_mse, (double)ss[0]);
    }
}

// ---------------- kernel 2: fused 4-accumulator (5-product) GEMM + argmin ---
// accN = Mb.Mb^T                  accG = MH.MH^T
// accP = (MH+Mb).(MH-Mb)^T   =>   s1 = G - n - P
// accQ = MH2.Mb^T + Mb.MH2^T =>   s2 = Q - 2G
extern __shared__ char dynsmem[];

__global__ __launch_bounds__(128, 2)
void gemm_kernel() {
    const int bi = blockIdx.y, bj = blockIdx.x;
    if (bj < bi) return;                        // upper triangle incl diagonal

    const int tid  = threadIdx.x;
    const int lane = tid & 31;
    const int warp = tid >> 5;                  // 0..3
    const int wm = warp >> 1;                   // 0..1 -> 32-row slab
    const int wn = warp & 1;                    // 0..1 -> 32-col slab
    const int g  = lane >> 2;
    const int tg = lane & 3;
    const int ib = bi * BM, jb = bj * BN;

    unsigned raw = (unsigned)__cvta_generic_to_shared(dynsmem);
    unsigned sb0 = (raw + 1023u) & ~1023u;      // 1024-aligned stage area
    char* auxg = dynsmem + (sb0 - raw);
    unsigned long long* keyI = (unsigned long long*)(auxg + KEYI_OFF);
    unsigned long long* keyJ = (unsigned long long*)(auxg + KEYJ_OFF);
    int* s_amJ = (int*)(auxg + AMJ_OFF);

    if (tid < BM)            keyI[tid] = ~0ull;
    else {                   keyJ[tid - BM] = ~0ull; s_amJ[tid - BM] = g_am[jb + tid - BM]; }

    float accN[2][4][4], accG[2][4][4], accP[2][4][4], accQ[2][4][4];
    #pragma unroll
    for (int a = 0; a < 2; a++)
        #pragma unroll
        for (int b = 0; b < 4; b++)
            #pragma unroll
            for (int c = 0; c < 4; c++) {
                accN[a][b][c] = 0.f; accG[a][b][c] = 0.f;
                accP[a][b][c] = 0.f; accQ[a][b][c] = 0.f;
            }

    const __nv_bfloat16* const mats[3] = {g_Mb, g_MH, g_MH2};

    // ---- stage loader: 6 tiles (3 A rows=ib, 3 B rows=jb) x 64 rows x 8 chunks
    auto load_stage = [&](int stage, int kt) {
        unsigned sb = sb0 + stage * STAGE_BYTES;
        int kcol = kt * BK;
        #pragma unroll
        for (int it = 0; it < 24; it++) {          // 6*64*8 = 3072 chunks / 128 thr
            int id = tid + it * 128;
            int op = id >> 9;                      // 0..5
            int rem = id & 511, r = rem >> 3, c = rem & 7;
            int rowbase = (op < 3) ? ib : jb;
            const __nv_bfloat16* gp = mats[op % 3] + (size_t)(rowbase + r) * D_DIM + kcol + c * 8;
            cp_async16(sb + op * OP_BYTES + r * 128 + (((unsigned)(c ^ (r & 7))) << 4), gp);
        }
    };

    // ldmatrix per-lane geometry
    const int a_lrow = lane & 15;
    const int a_half = lane >> 4;
    const int b_lrow = (lane & 7) + ((lane >> 4) << 3);
    const int b_half = (lane >> 3) & 1;

    load_stage(0, 0);
    cp_commit();

    #pragma unroll 1
    for (int kt = 0; kt < NT; kt++) {
        if (kt + 1 < NT) { load_stage((kt + 1) & 1, kt + 1); cp_commit(); cp_wait1(); }
        else             { cp_wait0(); }
        __syncthreads();

        unsigned sb = sb0 + (kt & 1) * STAGE_BYTES;
        #pragma unroll
        for (int kk8 = 0; kk8 < 8; kk8 += 2) {      // 4 k-chunks of 16
            // B fragments: Mb, MH, MH2 (3 ops x 4 nf x 2 regs)
            unsigned bf[3][4][2];
            #pragma unroll
            for (int m = 0; m < 3; m++)
                #pragma unroll
                for (int ng = 0; ng < 2; ng++) {
                    int row = wn * 32 + ng * 16 + b_lrow;
                    unsigned addr = sb + B_OFF + m * OP_BYTES + row * 128
                                  + (((unsigned)((kk8 + b_half) ^ (row & 7))) << 4);
                    unsigned r[4]; ldsm_x4(r, addr);
                    bf[m][2 * ng][0] = r[0]; bf[m][2 * ng][1] = r[1];
                    bf[m][2 * ng + 1][0] = r[2]; bf[m][2 * ng + 1][1] = r[3];
                }
            // derived B: MH - Mb
            unsigned bms[4][2];
            #pragma unroll
            for (int nf = 0; nf < 4; nf++) {
                bms[nf][0] = hsub2u(bf[1][nf][0], bf[0][nf][0]);
                bms[nf][1] = hsub2u(bf[1][nf][1], bf[0][nf][1]);
            }
            // A fragments per mf row-slab
            #pragma unroll
            for (int mf = 0; mf < 2; mf++) {
                int row = wm * 32 + mf * 16 + a_lrow;
                unsigned arow_off = row * 128 + (((unsigned)((kk8 + a_half) ^ (row & 7))) << 4);
                unsigned aMb[4]; ldsm_x4(aMb, sb + 0 * OP_BYTES + arow_off);
                #pragma unroll
                for (int nf = 0; nf < 4; nf++) {
                    mma16816(accN[mf][nf], aMb, bf[0][nf]);   // n  += Mb.Mb
                    mma16816(accQ[mf][nf], aMb, bf[2][nf]);   // Q  += Mb.MH2
                }
                unsigned aMH[4]; ldsm_x4(aMH, sb + 1 * OP_BYTES + arow_off);
                #pragma unroll
                for (int nf = 0; nf < 4; nf++)
                    mma16816(accG[mf][nf], aMH, bf[1][nf]);   // G  += MH.MH
                unsigned aPS[4];
                #pragma unroll
                for (int q = 0; q < 4; q++) aPS[q] = hadd2u(aMH[q], aMb[q]);  // MH+Mb
                #pragma unroll
                for (int nf = 0; nf < 4; nf++)
                    mma16816(accP[mf][nf], aPS, bms[nf]);     // P  += (MH+Mb).(MH-Mb)
                unsigned aMH2[4]; ldsm_x4(aMH2, sb + 2 * OP_BYTES + arow_off);
                #pragma unroll
                for (int nf = 0; nf < 4; nf++)
                    mma16816(accQ[mf][nf], aMH2, bf[0][nf]);  // Q  += MH2.Mb
            }
        }
        __syncthreads();                            // protect stage before overwrite
    }

    // ---- epilogue: score + packed (score,index) min-reduction --------------
    unsigned long long rk[2][2] = {{~0ull, ~0ull}, {~0ull, ~0ull}};   // [mf][rr]
    unsigned long long ck[4][2] = {{~0ull,~0ull},{~0ull,~0ull},{~0ull,~0ull},{~0ull,~0ull}};

    #pragma unroll
    for (int mf = 0; mf < 2; mf++) {
        const int i0 = ib + wm * 32 + mf * 16 + g;
        const int am0 = g_am[i0];
        const int am1 = g_am[i0 + 8];
        #pragma unroll
        for (int nf = 0; nf < 4; nf++)
            #pragma unroll
            for (int idx = 0; idx < 4; idx++) {
                int rr = idx >> 1, c = idx & 1;
                int i = i0 + rr * 8;
                int jl = wn * 32 + nf * 8 + tg * 2 + c;
                int j = jb + jl;
                float nn = accN[mf][nf][idx];
                int ami = rr ? am1 : am0;
                if (i != j && nn > 1.5f && ami != s_amJ[jl]) {
                    float ns = fmaxf(nn, 2.f);
                    float gg = accG[mf][nf][idx];
                    float s1 = gg - nn - accP[mf][nf][idx];
                    float s2 = accQ[mf][nf][idx] - 2.f * gg;
                    float var = (s2 - s1 * s1 / ns) / (ns - 1.f);
                    rk[mf][rr] = ullmin2(rk[mf][rr], pack_key(var, j));
                    ck[nf][c]  = ullmin2(ck[nf][c],  pack_key(var, i));
                }
            }
    }

    // row-side: min over quad lanes (same row, different cols)
    #pragma unroll
    for (int mf = 0; mf < 2; mf++)
        #pragma unroll
        for (int rr = 0; rr < 2; rr++) {
            unsigned long long v = rk[mf][rr];
            v = ullmin2(v, __shfl_xor_sync(0xffffffffu, v, 1));
            v = ullmin2(v, __shfl_xor_sync(0xffffffffu, v, 2));
            if (tg == 0 && v != ~0ull)
                atomicMin(&keyI[wm * 32 + mf * 16 + rr * 8 + g], v);
        }
    // col-side: min over lanes sharing tg (same cols, different rows)
    #pragma unroll
    for (int nf = 0; nf < 4; nf++)
        #pragma unroll
        for (int c = 0; c < 2; c++) {
            unsigned long long v = ck[nf][c];
            v = ullmin2(v, __shfl_down_sync(0xffffffffu, v, 4));
            v = ullmin2(v, __shfl_down_sync(0xffffffffu, v, 8));
            v = ullmin2(v, __shfl_down_sync(0xffffffffu, v, 16));
            if (g == 0 && v != ~0ull)
                atomicMin(&keyJ[wn * 32 + nf * 8 + tg * 2 + c], v);
        }

    __syncthreads();
    if (tid < BM) {
        if (keyI[tid] != ~0ull) atomicMin(&g_rowmin[ib + tid], keyI[tid]);
    } else {
        if (keyJ[tid - BM] != ~0ull) atomicMin(&g_rowmin[jb + tid - BM], keyJ[tid - BM]);
    }
}

// ---------------- kernel 3: row loss ||H[i] - H[argmin]|| -------------------
__global__ void rowloss_kernel(const float* __restrict__ H) {
    int i = blockIdx.x;
    int t = threadIdx.x;                           // 256 threads x float4
    int j = (int)(g_rowmin[i] & 0xFFFFFFFFull);
    float4 va = *(const float4*)(H + (size_t)i * D_DIM + t * 4);
    float4 vb = *(const float4*)(H + (size_t)j * D_DIM + t * 4);
    float dx = va.x - vb.x, dy = va.y - vb.y, dz = va.z - vb.z, dw = va.w - vb.w;
    float s = dx * dx + dy * dy + dz * dz + dw * dw;
    #pragma unroll
    for (int off = 16; off > 0; off >>= 1)
        s += __shfl_xor_sync(0xffffffffu, s, off);
    __shared__ float sw[8];
    if ((t & 31) == 0) sw[t >> 5] = s;
    __syncthreads();
    if (t == 0) {
        float tot = sw[0] + sw[1] + sw[2] + sw[3] + sw[4] + sw[5] + sw[6] + sw[7];
        atomicAdd(&g_rowloss, sqrt((double)tot));
    }
}

// ---------------- kernel 4: combine -----------------------------------------
__global__ void final_kernel(float* out) {
    out[0] = (float)(g_mse + 10.0 * g_rowloss);
}

// ---------------- launch ------------------------------------------------------
extern "C" void kernel_launch(void* const* d_in, const int* in_sizes, int n_in,
                              void* d_out, int out_size) {
    const float* X = (const float*)d_in[0];
    const float* H = (const float*)d_in[1];
    const float* C = (const float*)d_in[2];
    const float* M = (const float*)d_in[3];
    (void)in_sizes; (void)n_in; (void)out_size;

    cudaFuncSetAttribute(gemm_kernel, cudaFuncAttributeMaxDynamicSharedMemorySize, SMEM_REQ);

    init_kernel<<<(T_DIM + 255) / 256, 256>>>();
    prep_kernel<<<T_DIM, 256>>>(X, H, C, M);
    dim3 grid(T_DIM / BN, T_DIM / BM);             // (64, 64), bj < bi exits early
    gemm_kernel<<<grid, 128, SMEM_REQ>>>();
    rowloss_kernel<<<T_DIM, 256>>>(H);
    final_kernel<<<1, 1>>>((float*)d_out);
}

// round 8
// speedup vs baseline: 1.4687x; 1.1112x over previous
#include <cuda_runtime.h>
#include <cuda_bf16.h>
#include <math.h>
#include <stdint.h>

// Problem constants (fixed shapes per reference)
#define T_DIM 4096
#define D_DIM 1024
#define BM    64
#define BN    64
#define BK    64
#define NT    (D_DIM / BK)          // 16 k-tiles

#define OP_BYTES   (64 * 128)       // one MH tile: 64 rows x 128B (BK=64 bf16)
#define B_OFF      OP_BYTES
#define STAGE_BYTES (2 * OP_BYTES)  // 16384 (A-MH + B-MH)
#define NSTAGE 4

#define AUX_OFF   (NSTAGE * STAGE_BYTES)    // 65536
#define KEYI_OFF  (AUX_OFF)                 // 64*8 = 512
#define KEYJ_OFF  (AUX_OFF + 512)           // 64*8 = 512
#define AMJ_OFF   (AUX_OFF + 1024)          // 64*4 = 256
#define AUX_BYTES 1280
#define SMEM_REQ  (AUX_OFF + AUX_BYTES + 1008)

// ---------------- scratch (static device allocations; no cudaMalloc) -------
__device__ __nv_bfloat16 g_MH [T_DIM * D_DIM];
__device__ int                g_am[T_DIM];
__device__ unsigned long long g_rowmin[T_DIM];
__device__ double             g_mse;
__device__ double             g_rowloss;

// ---------------- helpers ---------------------------------------------------
__device__ __forceinline__ unsigned long long pack_key(float s, int idx) {
    unsigned int u = __float_as_uint(s);
    u = (u & 0x80000000u) ? ~u : (u | 0x80000000u);   // order-preserving float->uint
    return ((unsigned long long)u << 32) | (unsigned int)idx;
}
__device__ __forceinline__ unsigned long long ullmin2(unsigned long long a, unsigned long long b) {
    return a < b ? a : b;
}
__device__ __forceinline__ void mma16816(float* c, const unsigned* a, const unsigned* b) {
    asm volatile(
        "mma.sync.aligned.m16n8k16.row.col.f32.bf16.bf16.f32 "
        "{%0,%1,%2,%3}, {%4,%5,%6,%7}, {%8,%9}, {%0,%1,%2,%3};"
        : "+f"(c[0]), "+f"(c[1]), "+f"(c[2]), "+f"(c[3])
        : "r"(a[0]), "r"(a[1]), "r"(a[2]), "r"(a[3]), "r"(b[0]), "r"(b[1]));
}
__device__ __forceinline__ void ldsm_x4(unsigned* r, unsigned addr) {
    asm volatile("ldmatrix.sync.aligned.m8n8.x4.shared.b16 {%0,%1,%2,%3}, [%4];"
        : "=r"(r[0]), "=r"(r[1]), "=r"(r[2]), "=r"(r[3]) : "r"(addr));
}
__device__ __forceinline__ void cp_async16(unsigned saddr, const void* gaddr) {
    asm volatile("cp.async.cg.shared.global [%0], [%1], 16;" :: "r"(saddr), "l"(gaddr));
}
__device__ __forceinline__ void cp_commit() { asm volatile("cp.async.commit_group;"); }
__device__ __forceinline__ void cp_wait2()  { asm volatile("cp.async.wait_group 2;"); }
__device__ __forceinline__ void cp_wait1()  { asm volatile("cp.async.wait_group 1;"); }
__device__ __forceinline__ void cp_wait0()  { asm volatile("cp.async.wait_group 0;"); }

__device__ __forceinline__ unsigned hne2z(unsigned a) {        // 1.0 where != 0
    __nv_bfloat162 va = *reinterpret_cast<__nv_bfloat162*>(&a);
    __nv_bfloat162 z; *reinterpret_cast<unsigned*>(&z) = 0u;
    __nv_bfloat162 r = __hne2(va, z);
    return *reinterpret_cast<unsigned*>(&r);
}
__device__ __forceinline__ unsigned hadd2u(unsigned a, unsigned b) {
    __nv_bfloat162 va = *reinterpret_cast<__nv_bfloat162*>(&a);
    __nv_bfloat162 vb = *reinterpret_cast<__nv_bfloat162*>(&b);
    __nv_bfloat162 r = __hadd2(va, vb);
    return *reinterpret_cast<unsigned*>(&r);
}
__device__ __forceinline__ unsigned hsub2u(unsigned a, unsigned b) {
    __nv_bfloat162 va = *reinterpret_cast<__nv_bfloat162*>(&a);
    __nv_bfloat162 vb = *reinterpret_cast<__nv_bfloat162*>(&b);
    __nv_bfloat162 r = __hsub2(va, vb);
    return *reinterpret_cast<unsigned*>(&r);
}
__device__ __forceinline__ unsigned hmul2u(unsigned a, unsigned b) {
    __nv_bfloat162 va = *reinterpret_cast<__nv_bfloat162*>(&a);
    __nv_bfloat162 vb = *reinterpret_cast<__nv_bfloat162*>(&b);
    __nv_bfloat162 r = __hmul2(va, vb);
    return *reinterpret_cast<unsigned*>(&r);
}

// ---------------- kernel 0: reset accumulators / row-min keys ---------------
__global__ void init_kernel() {
    int t = blockIdx.x * blockDim.x + threadIdx.x;
    if (t < T_DIM) g_rowmin[t] = pack_key(9999.0f, 0);
    if (t == 0) { g_mse = 0.0; g_rowloss = 0.0; }
}

// ---------------- kernel 1: build bf16 MH, am[], masked MSE -----------------
__global__ void prep_kernel(const float* __restrict__ X, const float* __restrict__ H,
                            const float* __restrict__ C, const float* __restrict__ M) {
    int i = blockIdx.x;
    int t = threadIdx.x;                       // 256 threads, 4 elems each
    const size_t base = (size_t)i * D_DIM;
    float4 m4 = *(const float4*)(M + base + t * 4);
    float4 h4 = *(const float4*)(H + base + t * 4);
    float4 x4 = *(const float4*)(X + base + t * 4);
    float4 c4 = *(const float4*)(C + base + t * 4);

    float mv[4] = {m4.x, m4.y, m4.z, m4.w};
    float hv[4] = {h4.x, h4.y, h4.z, h4.w};
    float xv[4] = {x4.x, x4.y, x4.z, x4.w};
    float cv[4] = {c4.x, c4.y, c4.z, c4.w};

    __nv_bfloat16 oh[4];
    float bestv = 3.4e38f; int besti = 0;
    float msum = 0.f;
    #pragma unroll
    for (int q = 0; q < 4; q++) {
        float mb = (mv[q] > 0.f) ? 1.f : 0.f;
        oh[q] = __float2bfloat16(mb * hv[q]);
        float e = (xv[q] - (hv[q] - cv[q])) * mv[q];
        msum += e * e;
        if (mv[q] < bestv) { bestv = mv[q]; besti = t * 4 + q; }
    }
    *(uint2*)(g_MH + base + t * 4) = *(uint2*)oh;

    __shared__ float sv[256]; __shared__ int si[256]; __shared__ float ss[256];
    sv[t] = bestv; si[t] = besti; ss[t] = msum;
    __syncthreads();
    for (int o = 128; o > 0; o >>= 1) {
        if (t < o) {
            if (sv[t + o] < sv[t] || (sv[t + o] == sv[t] && si[t + o] < si[t])) {
                sv[t] = sv[t + o]; si[t] = si[t + o];
            }
            ss[t] += ss[t + o];
        }
        __syncthreads();
    }
    if (t == 0) {
        g_am[i] = si[0];
        atomicAdd(&g_mse, (double)ss[0]);
    }
}

// ---------------- kernel 2: MH-only fused GEMM + score argmin ---------------
// All operands derived from MH in registers:
//   Mb = hne2(MH,0), MH2 = MH*MH, PS = MH+Mb, MS = MH-Mb
// accN = Mb.Mb^T                  accG = MH.MH^T
// accP = PS.MS^T             =>   s1 = G - n - P
// accQ = MH2.Mb^T + Mb.MH2^T =>   s2 = Q - 2G
extern __shared__ char dynsmem[];

__global__ __launch_bounds__(128, 2)
void gemm_kernel() {
    const int bi = blockIdx.y, bj = blockIdx.x;
    if (bj < bi) return;                        // upper triangle incl diagonal

    const int tid  = threadIdx.x;
    const int lane = tid & 31;
    const int warp = tid >> 5;                  // 0..3
    const int wm = warp >> 1;                   // 0..1 -> 32-row slab
    const int wn = warp & 1;                    // 0..1 -> 32-col slab
    const int g  = lane >> 2;
    const int tg = lane & 3;
    const int ib = bi * BM, jb = bj * BN;

    unsigned raw = (unsigned)__cvta_generic_to_shared(dynsmem);
    unsigned sb0 = (raw + 1023u) & ~1023u;      // 1024-aligned stage area
    char* auxg = dynsmem + (sb0 - raw);
    unsigned long long* keyI = (unsigned long long*)(auxg + KEYI_OFF);
    unsigned long long* keyJ = (unsigned long long*)(auxg + KEYJ_OFF);
    int* s_amJ = (int*)(auxg + AMJ_OFF);

    if (tid < BM)            keyI[tid] = ~0ull;
    else {                   keyJ[tid - BM] = ~0ull; s_amJ[tid - BM] = g_am[jb + tid - BM]; }

    float accN[2][4][4], accG[2][4][4], accP[2][4][4], accQ[2][4][4];
    #pragma unroll
    for (int a = 0; a < 2; a++)
        #pragma unroll
        for (int b = 0; b < 4; b++)
            #pragma unroll
            for (int c = 0; c < 4; c++) {
                accN[a][b][c] = 0.f; accG[a][b][c] = 0.f;
                accP[a][b][c] = 0.f; accQ[a][b][c] = 0.f;
            }

    // ---- stage loader: 2 MH tiles (A rows=ib, B rows=jb) x 64 rows x 8 chunks
    auto load_stage = [&](int stage, int kt) {
        unsigned sb = sb0 + stage * STAGE_BYTES;
        int kcol = kt * BK;
        #pragma unroll
        for (int it = 0; it < 8; it++) {           // 2*64*8 = 1024 chunks / 128 thr
            int id = tid + it * 128;
            int op = id >> 9;                      // 0..1
            int rem = id & 511, r = rem >> 3, c = rem & 7;
            int rowbase = op ? jb : ib;
            const __nv_bfloat16* gp = g_MH + (size_t)(rowbase + r) * D_DIM + kcol + c * 8;
            cp_async16(sb + op * OP_BYTES + r * 128 + (((unsigned)(c ^ (r & 7))) << 4), gp);
        }
    };

    // ldmatrix per-lane geometry
    const int a_lrow = lane & 15;
    const int a_half = lane >> 4;
    const int b_lrow = (lane & 7) + ((lane >> 4) << 3);
    const int b_half = (lane >> 3) & 1;

    load_stage(0, 0); cp_commit();
    load_stage(1, 1); cp_commit();
    load_stage(2, 2); cp_commit();

    #pragma unroll 1
    for (int kt = 0; kt < NT; kt++) {
        if (kt <= NT - 3)      cp_wait2();      // all but 2 most-recent groups done
        else if (kt == NT - 2) cp_wait1();
        else                   cp_wait0();
        __syncthreads();                         // stage kt visible; compute kt-1 done
        if (kt + 3 < NT) { load_stage((kt + 3) & 3, kt + 3); cp_commit(); }

        unsigned sb = sb0 + (kt & 3) * STAGE_BYTES;
        #pragma unroll
        for (int kk8 = 0; kk8 < 8; kk8 += 2) {      // 4 k-chunks of 16
            // B fragments: MH + derived Mb, MH2, MS (4 nf x 2 regs each)
            unsigned bMH[4][2], bMb[4][2], bMH2[4][2], bMS[4][2];
            #pragma unroll
            for (int ng = 0; ng < 2; ng++) {
                int row = wn * 32 + ng * 16 + b_lrow;
                unsigned addr = sb + B_OFF + row * 128
                              + (((unsigned)((kk8 + b_half) ^ (row & 7))) << 4);
                unsigned r[4]; ldsm_x4(r, addr);
                bMH[2 * ng][0] = r[0]; bMH[2 * ng][1] = r[1];
                bMH[2 * ng + 1][0] = r[2]; bMH[2 * ng + 1][1] = r[3];
            }
            #pragma unroll
            for (int nf = 0; nf < 4; nf++)
                #pragma unroll
                for (int rr = 0; rr < 2; rr++) {
                    unsigned mh = bMH[nf][rr];
                    unsigned mb = hne2z(mh);
                    bMb[nf][rr]  = mb;
                    bMS[nf][rr]  = hsub2u(mh, mb);
                    bMH2[nf][rr] = hmul2u(mh, mh);
                }
            // A fragments per mf row-slab
            #pragma unroll
            for (int mf = 0; mf < 2; mf++) {
                int row = wm * 32 + mf * 16 + a_lrow;
                unsigned arow_off = row * 128 + (((unsigned)((kk8 + a_half) ^ (row & 7))) << 4);
                unsigned aMH[4]; ldsm_x4(aMH, sb + arow_off);
                unsigned aMb[4], aPS[4], aMH2[4];
                #pragma unroll
                for (int q = 0; q < 4; q++) {
                    aMb[q]  = hne2z(aMH[q]);
                    aPS[q]  = hadd2u(aMH[q], aMb[q]);
                    aMH2[q] = hmul2u(aMH[q], aMH[q]);
                }
                #pragma unroll
                for (int nf = 0; nf < 4; nf++) {
                    mma16816(accN[mf][nf], aMb,  bMb[nf]);    // n += Mb.Mb
                    mma16816(accG[mf][nf], aMH,  bMH[nf]);    // G += MH.MH
                    mma16816(accP[mf][nf], aPS,  bMS[nf]);    // P += (MH+Mb).(MH-Mb)
                    mma16816(accQ[mf][nf], aMb,  bMH2[nf]);   // Q += Mb.MH2
                    mma16816(accQ[mf][nf], aMH2, bMb[nf]);    // Q += MH2.Mb
                }
            }
        }
    }

    // ---- epilogue: score + packed (score,index) min-reduction --------------
    unsigned long long rk[2][2] = {{~0ull, ~0ull}, {~0ull, ~0ull}};   // [mf][rr]
    unsigned long long ck[4][2] = {{~0ull,~0ull},{~0ull,~0ull},{~0ull,~0ull},{~0ull,~0ull}};

    #pragma unroll
    for (int mf = 0; mf < 2; mf++) {
        const int i0 = ib + wm * 32 + mf * 16 + g;
        const int am0 = g_am[i0];
        const int am1 = g_am[i0 + 8];
        #pragma unroll
        for (int nf = 0; nf < 4; nf++)
            #pragma unroll
            for (int idx = 0; idx < 4; idx++) {
                int rr = idx >> 1, c = idx & 1;
                int i = i0 + rr * 8;
                int jl = wn * 32 + nf * 8 + tg * 2 + c;
                int j = jb + jl;
                float nn = accN[mf][nf][idx];
                int ami = rr ? am1 : am0;
                if (i != j && nn > 1.5f && ami != s_amJ[jl]) {
                    float ns = fmaxf(nn, 2.f);
                    float gg = accG[mf][nf][idx];
                    float s1 = gg - nn - accP[mf][nf][idx];
                    float s2 = accQ[mf][nf][idx] - 2.f * gg;
                    float var = (s2 - s1 * s1 / ns) / (ns - 1.f);
                    rk[mf][rr] = ullmin2(rk[mf][rr], pack_key(var, j));
                    ck[nf][c]  = ullmin2(ck[nf][c],  pack_key(var, i));
                }
            }
    }

    // row-side: min over quad lanes (same row, different cols)
    #pragma unroll
    for (int mf = 0; mf < 2; mf++)
        #pragma unroll
        for (int rr = 0; rr < 2; rr++) {
            unsigned long long v = rk[mf][rr];
            v = ullmin2(v, __shfl_xor_sync(0xffffffffu, v, 1));
            v = ullmin2(v, __shfl_xor_sync(0xffffffffu, v, 2));
            if (tg == 0 && v != ~0ull)
                atomicMin(&keyI[wm * 32 + mf * 16 + rr * 8 + g], v);
        }
    // col-side: min over lanes sharing tg (same cols, different rows)
    #pragma unroll
    for (int nf = 0; nf < 4; nf++)
        #pragma unroll
        for (int c = 0; c < 2; c++) {
            unsigned long long v = ck[nf][c];
            v = ullmin2(v, __shfl_down_sync(0xffffffffu, v, 4));
            v = ullmin2(v, __shfl_down_sync(0xffffffffu, v, 8));
            v = ullmin2(v, __shfl_down_sync(0xffffffffu, v, 16));
            if (g == 0 && v != ~0ull)
                atomicMin(&keyJ[wn * 32 + nf * 8 + tg * 2 + c], v);
        }

    __syncthreads();
    if (tid < BM) {
        if (keyI[tid] != ~0ull) atomicMin(&g_rowmin[ib + tid], keyI[tid]);
    } else {
        if (keyJ[tid - BM] != ~0ull) atomicMin(&g_rowmin[jb + tid - BM], keyJ[tid - BM]);
    }
}

// ---------------- kernel 3: row loss ||H[i] - H[argmin]|| -------------------
__global__ void rowloss_kernel(const float* __restrict__ H) {
    int i = blockIdx.x;
    int t = threadIdx.x;                           // 256 threads x float4
    int j = (int)(g_rowmin[i] & 0xFFFFFFFFull);
    float4 va = *(const float4*)(H + (size_t)i * D_DIM + t * 4);
    float4 vb = *(const float4*)(H + (size_t)j * D_DIM + t * 4);
    float dx = va.x - vb.x, dy = va.y - vb.y, dz = va.z - vb.z, dw = va.w - vb.w;
    float s = dx * dx + dy * dy + dz * dz + dw * dw;
    #pragma unroll
    for (int off = 16; off > 0; off >>= 1)
        s += __shfl_xor_sync(0xffffffffu, s, off);
    __shared__ float sw[8];
    if ((t & 31) == 0) sw[t >> 5] = s;
    __syncthreads();
    if (t == 0) {
        float tot = sw[0] + sw[1] + sw[2] + sw[3] + sw[4] + sw[5] + sw[6] + sw[7];
        atomicAdd(&g_rowloss, sqrt((double)tot));
    }
}

// ---------------- kernel 4: combine -----------------------------------------
__global__ void final_kernel(float* out) {
    out[0] = (float)(g_mse + 10.0 * g_rowloss);
}

// ---------------- launch ------------------------------------------------------
extern "C" void kernel_launch(void* const* d_in, const int* in_sizes, int n_in,
                              void* d_out, int out_size) {
    const float* X = (const float*)d_in[0];
    const float* H = (const float*)d_in[1];
    const float* C = (const float*)d_in[2];
    const float* M = (const float*)d_in[3];
    (void)in_sizes; (void)n_in; (void)out_size;

    cudaFuncSetAttribute(gemm_kernel, cudaFuncAttributeMaxDynamicSharedMemorySize, SMEM_REQ);

    init_kernel<<<(T_DIM + 255) / 256, 256>>>();
    prep_kernel<<<T_DIM, 256>>>(X, H, C, M);
    dim3 grid(T_DIM / BN, T_DIM / BM);             // (64, 64), bj < bi exits early
    gemm_kernel<<<grid, 128, SMEM_REQ>>>();
    rowloss_kernel<<<T_DIM, 256>>>(H);
    final_kernel<<<1, 1>>>((float*)d_out);
}

// round 9
// speedup vs baseline: 1.4780x; 1.0063x over previous
#include <cuda_runtime.h>
#include <cuda_bf16.h>
#include <math.h>
#include <stdint.h>

// Problem constants (fixed shapes per reference)
#define T_DIM 4096
#define D_DIM 1024
#define BM    64
#define BN    64
#define BK    128                   // bf16 elems per k-tile (256B per row)
#define NT    (D_DIM / BK)          // 8 k-tiles
#define NTILE (T_DIM / BM)          // 64

#define OP_BYTES   (64 * 256)       // one MH tile: 64 rows x 256B
#define B_OFF      OP_BYTES
#define STAGE_BYTES (2 * OP_BYTES)  // 32768 (A-MH + B-MH)
#define NSTAGE 3

#define AUX_OFF   (NSTAGE * STAGE_BYTES)    // 98304
#define KEYI_OFF  (AUX_OFF)                 // 64*8 = 512
#define KEYJ_OFF  (AUX_OFF + 512)           // 64*8 = 512
#define AMJ_OFF   (AUX_OFF + 1024)          // 64*4 = 256
#define AUX_BYTES 1280
#define SMEM_REQ  (AUX_OFF + AUX_BYTES + 1008)

// ---------------- scratch (static device allocations; no cudaMalloc) -------
__device__ __nv_bfloat16 g_MH [T_DIM * D_DIM];
__device__ int                g_am[T_DIM];
__device__ unsigned long long g_rowmin[T_DIM];
__device__ double             g_mse;
__device__ double             g_rowloss;

// ---------------- helpers ---------------------------------------------------
__device__ __forceinline__ unsigned long long pack_key(float s, int idx) {
    unsigned int u = __float_as_uint(s);
    u = (u & 0x80000000u) ? ~u : (u | 0x80000000u);   // order-preserving float->uint
    return ((unsigned long long)u << 32) | (unsigned int)idx;
}
__device__ __forceinline__ unsigned long long ullmin2(unsigned long long a, unsigned long long b) {
    return a < b ? a : b;
}
__device__ __forceinline__ void mma16816(float* c, const unsigned* a, const unsigned* b) {
    asm volatile(
        "mma.sync.aligned.m16n8k16.row.col.f32.bf16.bf16.f32 "
        "{%0,%1,%2,%3}, {%4,%5,%6,%7}, {%8,%9}, {%0,%1,%2,%3};"
        : "+f"(c[0]), "+f"(c[1]), "+f"(c[2]), "+f"(c[3])
        : "r"(a[0]), "r"(a[1]), "r"(a[2]), "r"(a[3]), "r"(b[0]), "r"(b[1]));
}
__device__ __forceinline__ void ldsm_x4(unsigned* r, unsigned addr) {
    asm volatile("ldmatrix.sync.aligned.m8n8.x4.shared.b16 {%0,%1,%2,%3}, [%4];"
        : "=r"(r[0]), "=r"(r[1]), "=r"(r[2]), "=r"(r[3]) : "r"(addr));
}
__device__ __forceinline__ void cp_async16(unsigned saddr, const void* gaddr) {
    asm volatile("cp.async.cg.shared.global [%0], [%1], 16;" :: "r"(saddr), "l"(gaddr));
}
__device__ __forceinline__ void cp_commit() { asm volatile("cp.async.commit_group;"); }
__device__ __forceinline__ void cp_wait1()  { asm volatile("cp.async.wait_group 1;"); }
__device__ __forceinline__ void cp_wait0()  { asm volatile("cp.async.wait_group 0;"); }

__device__ __forceinline__ unsigned hne2z(unsigned a) {        // 1.0 where != 0
    __nv_bfloat162 va = *reinterpret_cast<__nv_bfloat162*>(&a);
    __nv_bfloat162 z; *reinterpret_cast<unsigned*>(&z) = 0u;
    __nv_bfloat162 r = __hne2(va, z);
    return *reinterpret_cast<unsigned*>(&r);
}
__device__ __forceinline__ unsigned hadd2u(unsigned a, unsigned b) {
    __nv_bfloat162 va = *reinterpret_cast<__nv_bfloat162*>(&a);
    __nv_bfloat162 vb = *reinterpret_cast<__nv_bfloat162*>(&b);
    __nv_bfloat162 r = __hadd2(va, vb);
    return *reinterpret_cast<unsigned*>(&r);
}
__device__ __forceinline__ unsigned hsub2u(unsigned a, unsigned b) {
    __nv_bfloat162 va = *reinterpret_cast<__nv_bfloat162*>(&a);
    __nv_bfloat162 vb = *reinterpret_cast<__nv_bfloat162*>(&b);
    __nv_bfloat162 r = __hsub2(va, vb);
    return *reinterpret_cast<unsigned*>(&r);
}
__device__ __forceinline__ unsigned hmul2u(unsigned a, unsigned b) {
    __nv_bfloat162 va = *reinterpret_cast<__nv_bfloat162*>(&a);
    __nv_bfloat162 vb = *reinterpret_cast<__nv_bfloat162*>(&b);
    __nv_bfloat162 r = __hmul2(va, vb);
    return *reinterpret_cast<unsigned*>(&r);
}

// swizzled byte offset within one 64x256B tile (chunk c in 0..15, row r)
__device__ __forceinline__ unsigned swz(int c, int r) {
    return (((unsigned)((c & 7) ^ (r & 7))) << 4) + ((unsigned)(c >> 3) << 7);
}

// ---------------- kernel 0: reset accumulators / row-min keys ---------------
__global__ void init_kernel() {
    int t = blockIdx.x * blockDim.x + threadIdx.x;
    if (t < T_DIM) g_rowmin[t] = pack_key(9999.0f, 0);
    if (t == 0) { g_mse = 0.0; g_rowloss = 0.0; }
}

// ---------------- kernel 1: build bf16 MH, am[], masked MSE -----------------
__global__ void prep_kernel(const float* __restrict__ X, const float* __restrict__ H,
                            const float* __restrict__ C, const float* __restrict__ M) {
    int i = blockIdx.x;
    int t = threadIdx.x;                       // 256 threads, 4 elems each
    const size_t base = (size_t)i * D_DIM;
    float4 m4 = *(const float4*)(M + base + t * 4);
    float4 h4 = *(const float4*)(H + base + t * 4);
    float4 x4 = *(const float4*)(X + base + t * 4);
    float4 c4 = *(const float4*)(C + base + t * 4);

    float mv[4] = {m4.x, m4.y, m4.z, m4.w};
    float hv[4] = {h4.x, h4.y, h4.z, h4.w};
    float xv[4] = {x4.x, x4.y, x4.z, x4.w};
    float cv[4] = {c4.x, c4.y, c4.z, c4.w};

    __nv_bfloat16 oh[4];
    float bestv = 3.4e38f; int besti = 0;
    float msum = 0.f;
    #pragma unroll
    for (int q = 0; q < 4; q++) {
        float mb = (mv[q] > 0.f) ? 1.f : 0.f;
        oh[q] = __float2bfloat16(mb * hv[q]);
        float e = (xv[q] - (hv[q] - cv[q])) * mv[q];
        msum += e * e;
        if (mv[q] < bestv) { bestv = mv[q]; besti = t * 4 + q; }
    }
    *(uint2*)(g_MH + base + t * 4) = *(uint2*)oh;

    __shared__ float sv[256]; __shared__ int si[256]; __shared__ float ss[256];
    sv[t] = bestv; si[t] = besti; ss[t] = msum;
    __syncthreads();
    for (int o = 128; o > 0; o >>= 1) {
        if (t < o) {
            if (sv[t + o] < sv[t] || (sv[t + o] == sv[t] && si[t + o] < si[t])) {
                sv[t] = sv[t + o]; si[t] = si[t + o];
            }
            ss[t] += ss[t + o];
        }
        __syncthreads();
    }
    if (t == 0) {
        g_am[i] = si[0];
        atomicAdd(&g_mse, (double)ss[0]);
    }
}

// ---------------- kernel 2: MH-only fused GEMM + score argmin ---------------
// All operands derived from MH in registers:
//   Mb = hne2(MH,0), MH2 = MH*MH, PS = MH+Mb, MS = MH-Mb
// accN = Mb.Mb^T                  accG = MH.MH^T
// accP = PS.MS^T             =>   s1 = G - n - P
// accQ = MH2.Mb^T + Mb.MH2^T =>   s2 = Q - 2G
extern __shared__ char dynsmem[];

__global__ __launch_bounds__(128, 2)
void gemm_kernel() {
    // exact triangular cover: grid (NTILE+1, NTILE/2); rows y and NTILE-1-y
    // have lengths (NTILE-y)+(y+1) = NTILE+1, packed into one grid row.
    int bi, bj;
    {
        int x = blockIdx.x, y = blockIdx.y;
        int len0 = NTILE - y;
        if (x < len0) { bi = y;             bj = y + x; }
        else          { bi = NTILE - 1 - y; bj = bi + (x - len0); }
    }

    const int tid  = threadIdx.x;
    const int lane = tid & 31;
    const int warp = tid >> 5;                  // 0..3
    const int wm = warp >> 1;                   // 0..1 -> 32-row slab
    const int wn = warp & 1;                    // 0..1 -> 32-col slab
    const int g  = lane >> 2;
    const int tg = lane & 3;
    const int ib = bi * BM, jb = bj * BN;

    unsigned raw = (unsigned)__cvta_generic_to_shared(dynsmem);
    unsigned sb0 = (raw + 1023u) & ~1023u;      // 1024-aligned stage area
    char* auxg = dynsmem + (sb0 - raw);
    unsigned long long* keyI = (unsigned long long*)(auxg + KEYI_OFF);
    unsigned long long* keyJ = (unsigned long long*)(auxg + KEYJ_OFF);
    int* s_amJ = (int*)(auxg + AMJ_OFF);

    if (tid < BM)            keyI[tid] = ~0ull;
    else {                   keyJ[tid - BM] = ~0ull; s_amJ[tid - BM] = g_am[jb + tid - BM]; }

    float accN[2][4][4], accG[2][4][4], accP[2][4][4], accQ[2][4][4];
    #pragma unroll
    for (int a = 0; a < 2; a++)
        #pragma unroll
        for (int b = 0; b < 4; b++)
            #pragma unroll
            for (int c = 0; c < 4; c++) {
                accN[a][b][c] = 0.f; accG[a][b][c] = 0.f;
                accP[a][b][c] = 0.f; accQ[a][b][c] = 0.f;
            }

    // ---- stage loader: 2 MH tiles (A rows=ib, B rows=jb) x 64 rows x 16 chunks
    auto load_stage = [&](int stage, int kt) {
        unsigned sb = sb0 + stage * STAGE_BYTES;
        int kcol = kt * BK;
        #pragma unroll
        for (int it = 0; it < 16; it++) {          // 2*64*16 = 2048 chunks / 128 thr
            int id = tid + it * 128;
            int op = id >> 10;                     // 0..1
            int rem = id & 1023, r = rem >> 4, c = rem & 15;
            int rowbase = op ? jb : ib;
            const __nv_bfloat16* gp = g_MH + (size_t)(rowbase + r) * D_DIM + kcol + c * 8;
            cp_async16(sb + op * OP_BYTES + r * 256 + swz(c, r), gp);
        }
    };

    // ldmatrix per-lane geometry
    const int a_lrow = lane & 15;
    const int a_half = lane >> 4;
    const int b_lrow = (lane & 7) + ((lane >> 4) << 3);
    const int b_half = (lane >> 3) & 1;

    load_stage(0, 0); cp_commit();
    load_stage(1, 1); cp_commit();

    #pragma unroll 1
    for (int kt = 0; kt < NT; kt++) {
        if (kt < NT - 1) cp_wait1(); else cp_wait0();   // stage kt resident
        __syncthreads();                                 // kt-1 consumption done
        if (kt + 2 < NT) { load_stage((kt + 2) % NSTAGE, kt + 2); cp_commit(); }

        unsigned sb = sb0 + (kt % NSTAGE) * STAGE_BYTES;
        #pragma unroll
        for (int kk8 = 0; kk8 < 16; kk8 += 2) {      // 8 k-chunks of 16
            // B fragments: MH + derived Mb, MH2, MS (4 nf x 2 regs each)
            unsigned bMH[4][2], bMb[4][2], bMH2[4][2], bMS[4][2];
            #pragma unroll
            for (int ng = 0; ng < 2; ng++) {
                int row = wn * 32 + ng * 16 + b_lrow;
                unsigned addr = sb + B_OFF + row * 256 + swz(kk8 + b_half, row);
                unsigned r[4]; ldsm_x4(r, addr);
                bMH[2 * ng][0] = r[0]; bMH[2 * ng][1] = r[1];
                bMH[2 * ng + 1][0] = r[2]; bMH[2 * ng + 1][1] = r[3];
            }
            #pragma unroll
            for (int nf = 0; nf < 4; nf++)
                #pragma unroll
                for (int rr = 0; rr < 2; rr++) {
                    unsigned mh = bMH[nf][rr];
                    unsigned mb = hne2z(mh);
                    bMb[nf][rr]  = mb;
                    bMS[nf][rr]  = hsub2u(mh, mb);
                    bMH2[nf][rr] = hmul2u(mh, mh);
                }
            // A fragments per mf row-slab
            #pragma unroll
            for (int mf = 0; mf < 2; mf++) {
                int row = wm * 32 + mf * 16 + a_lrow;
                unsigned arow_off = row * 256 + swz(kk8 + a_half, row);
                unsigned aMH[4]; ldsm_x4(aMH, sb + arow_off);
                unsigned aMb[4], aPS[4], aMH2[4];
                #pragma unroll
                for (int q = 0; q < 4; q++) {
                    aMb[q]  = hne2z(aMH[q]);
                    aPS[q]  = hadd2u(aMH[q], aMb[q]);
                    aMH2[q] = hmul2u(aMH[q], aMH[q]);
                }
                #pragma unroll
                for (int nf = 0; nf < 4; nf++) {
                    mma16816(accN[mf][nf], aMb,  bMb[nf]);    // n += Mb.Mb
                    mma16816(accG[mf][nf], aMH,  bMH[nf]);    // G += MH.MH
                    mma16816(accP[mf][nf], aPS,  bMS[nf]);    // P += (MH+Mb).(MH-Mb)
                    mma16816(accQ[mf][nf], aMb,  bMH2[nf]);   // Q += Mb.MH2
                    mma16816(accQ[mf][nf], aMH2, bMb[nf]);    // Q += MH2.Mb
                }
            }
        }
    }

    // ---- epilogue: score + packed (score,index) min-reduction --------------
    unsigned long long rk[2][2] = {{~0ull, ~0ull}, {~0ull, ~0ull}};   // [mf][rr]
    unsigned long long ck[4][2] = {{~0ull,~0ull},{~0ull,~0ull},{~0ull,~0ull},{~0ull,~0ull}};

    #pragma unroll
    for (int mf = 0; mf < 2; mf++) {
        const int i0 = ib + wm * 32 + mf * 16 + g;
        const int am0 = g_am[i0];
        const int am1 = g_am[i0 + 8];
        #pragma unroll
        for (int nf = 0; nf < 4; nf++)
            #pragma unroll
            for (int idx = 0; idx < 4; idx++) {
                int rr = idx >> 1, c = idx & 1;
                int i = i0 + rr * 8;
                int jl = wn * 32 + nf * 8 + tg * 2 + c;
                int j = jb + jl;
                float nn = accN[mf][nf][idx];
                int ami = rr ? am1 : am0;
                if (i != j && nn > 1.5f && ami != s_amJ[jl]) {
                    float ns = fmaxf(nn, 2.f);
                    float gg = accG[mf][nf][idx];
                    float s1 = gg - nn - accP[mf][nf][idx];
                    float s2 = accQ[mf][nf][idx] - 2.f * gg;
                    float var = (s2 - s1 * s1 / ns) / (ns - 1.f);
                    rk[mf][rr] = ullmin2(rk[mf][rr], pack_key(var, j));
                    ck[nf][c]  = ullmin2(ck[nf][c],  pack_key(var, i));
                }
            }
    }

    // row-side: min over quad lanes (same row, different cols)
    #pragma unroll
    for (int mf = 0; mf < 2; mf++)
        #pragma unroll
        for (int rr = 0; rr < 2; rr++) {
            unsigned long long v = rk[mf][rr];
            v = ullmin2(v, __shfl_xor_sync(0xffffffffu, v, 1));
            v = ullmin2(v, __shfl_xor_sync(0xffffffffu, v, 2));
            if (tg == 0 && v != ~0ull)
                atomicMin(&keyI[wm * 32 + mf * 16 + rr * 8 + g], v);
        }
    // col-side: min over lanes sharing tg (same cols, different rows)
    #pragma unroll
    for (int nf = 0; nf < 4; nf++)
        #pragma unroll
        for (int c = 0; c < 2; c++) {
            unsigned long long v = ck[nf][c];
            v = ullmin2(v, __shfl_down_sync(0xffffffffu, v, 4));
            v = ullmin2(v, __shfl_down_sync(0xffffffffu, v, 8));
            v = ullmin2(v, __shfl_down_sync(0xffffffffu, v, 16));
            if (g == 0 && v != ~0ull)
                atomicMin(&keyJ[wn * 32 + nf * 8 + tg * 2 + c], v);
        }

    __syncthreads();
    if (tid < BM) {
        if (keyI[tid] != ~0ull) atomicMin(&g_rowmin[ib + tid], keyI[tid]);
    } else {
        if (keyJ[tid - BM] != ~0ull) atomicMin(&g_rowmin[jb + tid - BM], keyJ[tid - BM]);
    }
}

// ---------------- kernel 3: row loss ||H[i] - H[argmin]|| -------------------
__global__ void rowloss_kernel(const float* __restrict__ H) {
    int i = blockIdx.x;
    int t = threadIdx.x;                           // 256 threads x float4
    int j = (int)(g_rowmin[i] & 0xFFFFFFFFull);
    float4 va = *(const float4*)(H + (size_t)i * D_DIM + t * 4);
    float4 vb = *(const float4*)(H + (size_t)j * D_DIM + t * 4);
    float dx = va.x - vb.x, dy = va.y - vb.y, dz = va.z - vb.z, dw = va.w - vb.w;
    float s = dx * dx + dy * dy + dz * dz + dw * dw;
    #pragma unroll
    for (int off = 16; off > 0; off >>= 1)
        s += __shfl_xor_sync(0xffffffffu, s, off);
    __shared__ float sw[8];
    if ((t & 31) == 0) sw[t >> 5] = s;
    __syncthreads();
    if (t == 0) {
        float tot = sw[0] + sw[1] + sw[2] + sw[3] + sw[4] + sw[5] + sw[6] + sw[7];
        atomicAdd(&g_rowloss, sqrt((double)tot));
    }
}

// ---------------- kernel 4: combine -----------------------------------------
__global__ void final_kernel(float* out) {
    out[0] = (float)(g_mse + 10.0 * g_rowloss);
}

// ---------------- launch ------------------------------------------------------
extern "C" void kernel_launch(void* const* d_in, const int* in_sizes, int n_in,
                              void* d_out, int out_size) {
    const float* X = (const float*)d_in[0];
    const float* H = (const float*)d_in[1];
    const float* C = (const float*)d_in[2];
    const float* M = (const float*)d_in[3];
    (void)in_sizes; (void)n_in; (void)out_size;

    cudaFuncSetAttribute(gemm_kernel, cudaFuncAttributeMaxDynamicSharedMemorySize, SMEM_REQ);

    init_kernel<<<(T_DIM + 255) / 256, 256>>>();
    prep_kernel<<<T_DIM, 256>>>(X, H, C, M);
    dim3 grid(NTILE + 1, NTILE / 2);               // (65, 32) exact triangle cover
    gemm_kernel<<<grid, 128, SMEM_REQ>>>();
    rowloss_kernel<<<T_DIM, 256>>>(H);
    final_kernel<<<1, 1>>>((float*)d_out);
}